// round 8
// baseline (speedup 1.0000x reference)
#include <cuda_runtime.h>
#include <cstdint>
#include <cstddef>

#define BATCH 2048
#define NN    14
#define INF   2048
#define OUTF  1024
#define MROWS (BATCH * NN)
#define WN    (2 * OUTF)

// Emulate CPU (MXCSR FTZ) flush-to-zero for the nonnegative tiny values in
// softmax/sinkhorn: anything below FLT_MIN (min normal) becomes exactly 0.
__device__ __forceinline__ float ftzf(float x) {
    return (x < 1.17549435e-38f) ? 0.f : x;
}

__device__ float g_Wpack[INF * WN];
__device__ float g_bpack[WN];
__device__ float g_Y1[MROWS * WN];
__device__ float g_Y2[MROWS * WN];
__device__ float g_e1[MROWS * OUTF];
__device__ float g_e2[MROWS * OUTF];
__device__ float g_M1[MROWS * OUTF];

__global__ void pack_w_kernel(const float* __restrict__ aw, const float* __restrict__ ab,
                              const float* __restrict__ uw, const float* __restrict__ ub)
{
    int idx = blockIdx.x * blockDim.x + threadIdx.x;
    if (idx < INF * OUTF) {
        int k = idx >> 10, n = idx & 1023;
        g_Wpack[k * WN + n]        = aw[idx];
        g_Wpack[k * WN + OUTF + n] = uw[idx];
    }
    if (idx < OUTF) { g_bpack[idx] = ab[idx]; g_bpack[OUTF + idx] = ub[idx]; }
}

// fp32 SGEMM, sequential-k accumulation per output element (Eigen gebp
// semantics). 128x128 tile, K-tile 16, 256 threads, 8x8/thread, dbl-buffered.
__global__ __launch_bounds__(256, 2)
void sgemm_kernel(const float* __restrict__ A, const float* __restrict__ B,
                  float* __restrict__ C, int K, int N,
                  const float* __restrict__ bias, int do_relu)
{
    __shared__ float As[2][16][132];
    __shared__ float Bs[2][16][128];

    const int tid = threadIdx.x, bm = blockIdx.y, bn = blockIdx.x;
    const float* Ab = A + (size_t)bm * 128 * K;
    const float* Bb = B + (size_t)bn * 128;

    const int arow = tid >> 2, acol = (tid & 3) * 4;
    const int brow = tid >> 5, bcol = (tid & 31) * 4;
    const int tx = tid & 15, ty = tid >> 4;

    float acc[8][8];
#pragma unroll
    for (int i = 0; i < 8; i++)
#pragma unroll
        for (int j = 0; j < 8; j++) acc[i][j] = 0.f;

    const int nk = K >> 4;
    {
        float4 a0 = *(const float4*)(Ab + (size_t)arow * K + acol);
        float4 a1 = *(const float4*)(Ab + (size_t)(arow + 64) * K + acol);
        float4 b0 = *(const float4*)(Bb + (size_t)brow * N + bcol);
        float4 b1 = *(const float4*)(Bb + (size_t)(brow + 8) * N + bcol);
        As[0][acol+0][arow] = a0.x; As[0][acol+1][arow] = a0.y;
        As[0][acol+2][arow] = a0.z; As[0][acol+3][arow] = a0.w;
        As[0][acol+0][arow+64] = a1.x; As[0][acol+1][arow+64] = a1.y;
        As[0][acol+2][arow+64] = a1.z; As[0][acol+3][arow+64] = a1.w;
        *(float4*)&Bs[0][brow][bcol]     = b0;
        *(float4*)&Bs[0][brow + 8][bcol] = b1;
    }
    __syncthreads();

    for (int kt = 0; kt < nk; kt++) {
        const int cur = kt & 1, nxt = cur ^ 1;
        float4 na0, na1, nb0, nb1;
        const bool has_next = (kt + 1 < nk);
        if (has_next) {
            const float* Ap = Ab + (size_t)(kt + 1) * 16;
            const float* Bp = Bb + (size_t)(kt + 1) * 16 * N;
            na0 = *(const float4*)(Ap + (size_t)arow * K + acol);
            na1 = *(const float4*)(Ap + (size_t)(arow + 64) * K + acol);
            nb0 = *(const float4*)(Bp + (size_t)brow * N + bcol);
            nb1 = *(const float4*)(Bp + (size_t)(brow + 8) * N + bcol);
        }
#pragma unroll
        for (int kk = 0; kk < 16; kk++) {
            float a[8], b[8];
#pragma unroll
            for (int i = 0; i < 4; i++) {
                a[i]     = As[cur][kk][ty * 4 + i];
                a[4 + i] = As[cur][kk][64 + ty * 4 + i];
                b[i]     = Bs[cur][kk][tx * 4 + i];
                b[4 + i] = Bs[cur][kk][64 + tx * 4 + i];
            }
#pragma unroll
            for (int i = 0; i < 8; i++)
#pragma unroll
                for (int j = 0; j < 8; j++)
                    acc[i][j] = fmaf(a[i], b[j], acc[i][j]);
        }
        if (has_next) {
            As[nxt][acol+0][arow] = na0.x; As[nxt][acol+1][arow] = na0.y;
            As[nxt][acol+2][arow] = na0.z; As[nxt][acol+3][arow] = na0.w;
            As[nxt][acol+0][arow+64] = na1.x; As[nxt][acol+1][arow+64] = na1.y;
            As[nxt][acol+2][arow+64] = na1.z; As[nxt][acol+3][arow+64] = na1.w;
            *(float4*)&Bs[nxt][brow][bcol]     = nb0;
            *(float4*)&Bs[nxt][brow + 8][bcol] = nb1;
            __syncthreads();
        }
    }

    const int row0 = bm * 128, col0 = bn * 128;
    float bb[8];
    if (bias) {
#pragma unroll
        for (int j = 0; j < 4; j++) {
            bb[j]     = bias[col0 + tx * 4 + j];
            bb[4 + j] = bias[col0 + 64 + tx * 4 + j];
        }
    } else {
#pragma unroll
        for (int j = 0; j < 8; j++) bb[j] = 0.f;
    }
#pragma unroll
    for (int i = 0; i < 8; i++) {
        int m = (i < 4) ? (ty * 4 + i) : (64 + ty * 4 + (i - 4));
        float* Crow = C + (size_t)(row0 + m) * N + col0;
        float v[8];
#pragma unroll
        for (int j = 0; j < 8; j++) {
            float x = __fadd_rn(acc[i][j], bb[j]);
            v[j] = do_relu ? fmaxf(x, 0.f) : x;
        }
        *(float4*)(Crow + tx * 4)      = make_float4(v[0], v[1], v[2], v[3]);
        *(float4*)(Crow + 64 + tx * 4) = make_float4(v[4], v[5], v[6], v[7]);
    }
}

// Gconv: e = bmm(Anorm, AX) + UX (dot from zero, then elementwise add).
__global__ void gconv_kernel(const float* __restrict__ adj, const float* __restrict__ Y,
                             float* __restrict__ e)
{
    const int b = blockIdx.x, tid = threadIdx.x;
    __shared__ float sA[NN * NN];
    __shared__ float cs[NN];
    __shared__ float An[NN][NN + 2];

    if (tid < NN * NN) sA[tid] = adj[(size_t)b * NN * NN + tid];
    __syncthreads();
    if (tid < NN) {
        float s = 0.f;
#pragma unroll
        for (int i = 0; i < NN; i++) s = __fadd_rn(s, sA[i * NN + tid]);
        cs[tid] = fmaxf(s, 1e-12f);
    }
    __syncthreads();
    if (tid < NN * NN) {
        int i = tid / NN, j = tid - i * NN;
        An[i][j] = __fdiv_rn(sA[tid], cs[j]);
    }
    __syncthreads();

    const float* Yb = Y + (size_t)b * NN * WN;
    float* eb = e + (size_t)b * NN * OUTF;
    for (int f = tid; f < OUTF; f += blockDim.x) {
        float ax[NN], ux[NN];
#pragma unroll
        for (int j = 0; j < NN; j++) {
            ax[j] = Yb[j * WN + f];
            ux[j] = Yb[j * WN + OUTF + f];
        }
#pragma unroll
        for (int i = 0; i < NN; i++) {
            float d = __fmul_rn(An[i][0], ax[0]);
#pragma unroll
            for (int j = 1; j < NN; j++) d = fmaf(An[i][j], ax[j], d);
            eb[i * OUTF + f] = __fadd_rn(d, ux[i]);
        }
    }
}

// Affinity gram (sequential fp32) + softmax(200*s) + 20 Sinkhorn iters,
// with FTZ emulation on every tiny-value production site (exp results and
// normalization quotients) to match the CPU reference's MXCSR FTZ behavior.
__global__ void affinity_kernel(const float* __restrict__ Mx, const float* __restrict__ E2,
                                float* __restrict__ s_out)
{
    const int b = blockIdx.x, tid = threadIdx.x;
    __shared__ float sM[NN][129];
    __shared__ float sE[NN][129];
    __shared__ float S[NN][NN + 1];

    const float* Mb = Mx + (size_t)b * NN * OUTF;
    const float* Eb = E2 + (size_t)b * NN * OUTF;
    const int i = tid / NN, j = tid - i * NN;
    float acc = 0.f;

    for (int d0 = 0; d0 < OUTF; d0 += 128) {
        for (int t = tid; t < NN * 128; t += 256) {
            int r = t >> 7, c = t & 127;
            sM[r][c] = Mb[r * OUTF + d0 + c];
            sE[r][c] = Eb[r * OUTF + d0 + c];
        }
        __syncthreads();
        if (tid < NN * NN) {
#pragma unroll 8
            for (int c = 0; c < 128; c++)
                acc = fmaf(sM[i][c], sE[j][c], acc);
        }
        __syncthreads();
    }
    if (tid < NN * NN) S[i][j] = acc;
    __syncthreads();

    if (tid < NN) {
        float t[NN], m = -__int_as_float(0x7f800000);
#pragma unroll
        for (int jj = 0; jj < NN; jj++) {
            t[jj] = __fmul_rn(200.f, S[tid][jj]);
            m = fmaxf(m, t[jj]);
        }
        float p[NN], sum = 0.f;
#pragma unroll
        for (int jj = 0; jj < NN; jj++) {
            p[jj] = ftzf(expf(__fadd_rn(t[jj], -m)));   // FTZ: kill subnormal exps
            sum = __fadd_rn(sum, p[jj]);
        }
#pragma unroll
        for (int jj = 0; jj < NN; jj++)
            S[tid][jj] = ftzf(__fdiv_rn(p[jj], sum));   // FTZ on quotient
    }
    __syncthreads();

    for (int it = 0; it < 20; it++) {
        if ((it & 1) == 0) {
            if (tid < NN) {
                float sum = 0.f;
#pragma unroll
                for (int jj = 0; jj < NN; jj++) sum = __fadd_rn(sum, S[tid][jj]);
                sum = __fadd_rn(sum, 1e-10f);
#pragma unroll
                for (int jj = 0; jj < NN; jj++)
                    S[tid][jj] = ftzf(__fdiv_rn(S[tid][jj], sum));
            }
        } else {
            if (tid < NN) {
                float sum = 0.f;
#pragma unroll
                for (int ii = 0; ii < NN; ii++) sum = __fadd_rn(sum, S[ii][tid]);
                sum = __fadd_rn(sum, 1e-10f);
#pragma unroll
                for (int ii = 0; ii < NN; ii++)
                    S[ii][tid] = ftzf(__fdiv_rn(S[ii][tid], sum));
            }
        }
        __syncthreads();
    }
    if (tid < NN * NN) s_out[(size_t)b * NN * NN + tid] = S[i][j];
}

// Fusion: dot from zero over the contraction index, then add feat.
__global__ void fuse_kernel(const float* __restrict__ f1, const float* __restrict__ f2,
                            const float* __restrict__ s,
                            float* __restrict__ o1, float* __restrict__ o2)
{
    const int b = blockIdx.y;
    const int f = blockIdx.x * blockDim.x + threadIdx.x;
    __shared__ float S[NN * NN];
    if (threadIdx.x < NN * NN) S[threadIdx.x] = s[(size_t)b * NN * NN + threadIdx.x];
    __syncthreads();

    const float* f1b = f1 + (size_t)b * NN * INF;
    const float* f2b = f2 + (size_t)b * NN * INF;
    float* o1b = o1 + (size_t)b * NN * INF;
    float* o2b = o2 + (size_t)b * NN * INF;

    float x1[NN], x2[NN];
#pragma unroll
    for (int r = 0; r < NN; r++) { x1[r] = f1b[r * INF + f]; x2[r] = f2b[r * INF + f]; }
#pragma unroll
    for (int i = 0; i < NN; i++) {
        float d = __fmul_rn(S[i * NN], x2[0]);
#pragma unroll
        for (int jj = 1; jj < NN; jj++) d = fmaf(S[i * NN + jj], x2[jj], d);
        o1b[i * INF + f] = __fadd_rn(x1[i], d);
    }
#pragma unroll
    for (int jj = 0; jj < NN; jj++) {
        float d = __fmul_rn(S[jj], x1[0]);
#pragma unroll
        for (int ii = 1; ii < NN; ii++) d = fmaf(S[ii * NN + jj], x1[ii], d);
        o2b[jj * INF + f] = __fadd_rn(x2[jj], d);
    }
}

static float* symaddr(const void* sym) {
    void* p = nullptr;
    cudaGetSymbolAddress(&p, sym);
    return (float*)p;
}

extern "C" void kernel_launch(void* const* d_in, const int* in_sizes, int n_in,
                              void* d_out, int out_size)
{
    const float* feat1  = (const float*)d_in[0];
    const float* feat2  = (const float*)d_in[1];
    const float* adj    = (const float*)d_in[2];
    const float* a_fc_w = (const float*)d_in[3];
    const float* a_fc_b = (const float*)d_in[4];
    const float* u_fc_w = (const float*)d_in[5];
    const float* u_fc_b = (const float*)d_in[6];
    const float* aff_A  = (const float*)d_in[7];

    float* out   = (float*)d_out;
    float* s_out = out;
    float* out1  = out + (size_t)BATCH * NN * NN;
    float* out2  = out1 + (size_t)BATCH * NN * INF;

    float* Wp = symaddr(g_Wpack);
    float* bp = symaddr(g_bpack);
    float* Y1 = symaddr(g_Y1);
    float* Y2 = symaddr(g_Y2);
    float* e1 = symaddr(g_e1);
    float* e2 = symaddr(g_e2);
    float* M1 = symaddr(g_M1);

    pack_w_kernel<<<(INF * OUTF + 255) / 256, 256>>>(a_fc_w, a_fc_b, u_fc_w, u_fc_b);

    dim3 g1(WN / 128, MROWS / 128);
    sgemm_kernel<<<g1, 256>>>(feat1, Wp, Y1, INF, WN, bp, 1);
    sgemm_kernel<<<g1, 256>>>(feat2, Wp, Y2, INF, WN, bp, 1);

    gconv_kernel<<<BATCH, 256>>>(adj, Y1, e1);
    gconv_kernel<<<BATCH, 256>>>(adj, Y2, e2);

    dim3 g2(OUTF / 128, MROWS / 128);
    sgemm_kernel<<<g2, 256>>>(e1, aff_A, M1, OUTF, OUTF, nullptr, 0);

    affinity_kernel<<<BATCH, 256>>>(M1, e2, s_out);

    dim3 g3(INF / 256, BATCH);
    fuse_kernel<<<g3, 256>>>(feat1, feat2, s_out, out1, out2);
}

// round 9
// speedup vs baseline: 1.0956x; 1.0956x over previous
#include <cuda_runtime.h>
#include <cstdint>
#include <cstddef>

#define BATCH 2048
#define NN    14
#define INF   2048
#define OUTF  1024
#define MROWS (BATCH * NN)
#define WN    (2 * OUTF)

// CPU (MXCSR FTZ) emulation: nonnegative tiny values below FLT_MIN -> 0.
__device__ __forceinline__ float ftzf(float x) {
    return (x < 1.17549435e-38f) ? 0.f : x;
}

// Packed fp32 FMA (Blackwell f32x2). Each lane is an independent IEEE fp32
// fma.rn -> bitwise identical to two scalar fmaf chains.
__device__ __forceinline__ void ffma2(unsigned long long& d,
                                      unsigned long long a,
                                      unsigned long long b) {
    asm("fma.rn.f32x2 %0, %1, %2, %0;" : "+l"(d) : "l"(a), "l"(b));
}
__device__ __forceinline__ unsigned long long dup2(float x) {
    unsigned long long r;
    asm("mov.b64 %0, {%1, %1};" : "=l"(r) : "r"(__float_as_uint(x)));
    return r;
}
__device__ __forceinline__ float lo32(unsigned long long v) {
    return __uint_as_float((unsigned)(v & 0xffffffffull));
}
__device__ __forceinline__ float hi32(unsigned long long v) {
    return __uint_as_float((unsigned)(v >> 32));
}

__device__ float g_Wpack[INF * WN];
__device__ float g_bpack[WN];
__device__ float g_Y1[MROWS * WN];
__device__ float g_Y2[MROWS * WN];
__device__ float g_e1[MROWS * OUTF];
__device__ float g_e2[MROWS * OUTF];
__device__ float g_M1[MROWS * OUTF];

__global__ void pack_w_kernel(const float* __restrict__ aw, const float* __restrict__ ab,
                              const float* __restrict__ uw, const float* __restrict__ ub)
{
    int idx = blockIdx.x * blockDim.x + threadIdx.x;
    if (idx < INF * OUTF) {
        int k = idx >> 10, n = idx & 1023;
        g_Wpack[k * WN + n]        = aw[idx];
        g_Wpack[k * WN + OUTF + n] = uw[idx];
    }
    if (idx < OUTF) { g_bpack[idx] = ab[idx]; g_bpack[OUTF + idx] = ub[idx]; }
}

// fp32 SGEMM with sequential-k accumulation per output element (bitwise equal
// to an ascending-k fmaf chain). Inner loop uses fma.rn.f32x2: two M-rows
// packed per 64-bit accumulator, per-lane IEEE fp32 -> results bit-identical
// to the scalar version. 128x128 tile, K-tile 16, 256 thr, 8x8/thread.
__global__ __launch_bounds__(256, 2)
void sgemm_kernel(const float* __restrict__ A, const float* __restrict__ B,
                  float* __restrict__ C, int K, int N,
                  const float* __restrict__ bias, int do_relu)
{
    __shared__ float As[2][16][132];   // [kcol][row], row-contiguous
    __shared__ float Bs[2][16][128];

    const int tid = threadIdx.x, bm = blockIdx.y, bn = blockIdx.x;
    const float* Ab = A + (size_t)bm * 128 * K;
    const float* Bb = B + (size_t)bn * 128;

    const int arow = tid >> 2, acol = (tid & 3) * 4;
    const int brow = tid >> 5, bcol = (tid & 31) * 4;
    const int tx = tid & 15, ty = tid >> 4;

    // acc2[i2][j]: i2 packs row pair; mapping:
    // i2=0 -> rows ty*4+0 (lo), ty*4+1 (hi);  i2=1 -> ty*4+2, ty*4+3
    // i2=2 -> 64+ty*4+0, +1;                  i2=3 -> 64+ty*4+2, +3
    unsigned long long acc2[4][8];
#pragma unroll
    for (int i = 0; i < 4; i++)
#pragma unroll
        for (int j = 0; j < 8; j++) acc2[i][j] = 0ull;

    const int nk = K >> 4;
    {
        float4 a0 = *(const float4*)(Ab + (size_t)arow * K + acol);
        float4 a1 = *(const float4*)(Ab + (size_t)(arow + 64) * K + acol);
        float4 b0 = *(const float4*)(Bb + (size_t)brow * N + bcol);
        float4 b1 = *(const float4*)(Bb + (size_t)(brow + 8) * N + bcol);
        As[0][acol+0][arow] = a0.x; As[0][acol+1][arow] = a0.y;
        As[0][acol+2][arow] = a0.z; As[0][acol+3][arow] = a0.w;
        As[0][acol+0][arow+64] = a1.x; As[0][acol+1][arow+64] = a1.y;
        As[0][acol+2][arow+64] = a1.z; As[0][acol+3][arow+64] = a1.w;
        *(float4*)&Bs[0][brow][bcol]     = b0;
        *(float4*)&Bs[0][brow + 8][bcol] = b1;
    }
    __syncthreads();

    for (int kt = 0; kt < nk; kt++) {
        const int cur = kt & 1, nxt = cur ^ 1;
        float4 na0, na1, nb0, nb1;
        const bool has_next = (kt + 1 < nk);
        if (has_next) {
            const float* Ap = Ab + (size_t)(kt + 1) * 16;
            const float* Bp = Bb + (size_t)(kt + 1) * 16 * N;
            na0 = *(const float4*)(Ap + (size_t)arow * K + acol);
            na1 = *(const float4*)(Ap + (size_t)(arow + 64) * K + acol);
            nb0 = *(const float4*)(Bp + (size_t)brow * N + bcol);
            nb1 = *(const float4*)(Bp + (size_t)(brow + 8) * N + bcol);
        }
#pragma unroll
        for (int kk = 0; kk < 16; kk++) {
            // A rows as packed pairs: ty*4 is 16B-aligned; row stride 132
            // floats = 528B (16B multiple) -> ulonglong2 loads are LDS.128.
            ulonglong2 aA = *(const ulonglong2*)&As[cur][kk][ty * 4];
            ulonglong2 aB = *(const ulonglong2*)&As[cur][kk][64 + ty * 4];
            float4 b0 = *(const float4*)&Bs[cur][kk][tx * 4];
            float4 b1 = *(const float4*)&Bs[cur][kk][64 + tx * 4];
            unsigned long long ap[4] = { aA.x, aA.y, aB.x, aB.y };
            unsigned long long bp[8] = { dup2(b0.x), dup2(b0.y), dup2(b0.z), dup2(b0.w),
                                         dup2(b1.x), dup2(b1.y), dup2(b1.z), dup2(b1.w) };
#pragma unroll
            for (int i = 0; i < 4; i++)
#pragma unroll
                for (int j = 0; j < 8; j++)
                    ffma2(acc2[i][j], ap[i], bp[j]);
        }
        if (has_next) {
            As[nxt][acol+0][arow] = na0.x; As[nxt][acol+1][arow] = na0.y;
            As[nxt][acol+2][arow] = na0.z; As[nxt][acol+3][arow] = na0.w;
            As[nxt][acol+0][arow+64] = na1.x; As[nxt][acol+1][arow+64] = na1.y;
            As[nxt][acol+2][arow+64] = na1.z; As[nxt][acol+3][arow+64] = na1.w;
            *(float4*)&Bs[nxt][brow][bcol]     = nb0;
            *(float4*)&Bs[nxt][brow + 8][bcol] = nb1;
            __syncthreads();
        }
    }

    const int row0 = bm * 128, col0 = bn * 128;
    float bb[8];
    if (bias) {
#pragma unroll
        for (int j = 0; j < 4; j++) {
            bb[j]     = bias[col0 + tx * 4 + j];
            bb[4 + j] = bias[col0 + 64 + tx * 4 + j];
        }
    } else {
#pragma unroll
        for (int j = 0; j < 8; j++) bb[j] = 0.f;
    }
#pragma unroll
    for (int i = 0; i < 8; i++) {
        // old row index i -> (pair i>>1 within half, lane i&1)
        const int half = i >> 2;              // 0: rows ty*4+, 1: rows 64+ty*4+
        const int sub  = (i & 3) >> 1;        // which pair
        const int lane = i & 1;               // lo/hi
        const int i2 = half * 2 + sub;
        const int m = half * 64 + ty * 4 + (i & 3);
        float* Crow = C + (size_t)(row0 + m) * N + col0;
        float v[8];
#pragma unroll
        for (int j = 0; j < 8; j++) {
            float part = lane ? hi32(acc2[i2][j]) : lo32(acc2[i2][j]);
            float x = __fadd_rn(part, bb[j]);
            v[j] = do_relu ? fmaxf(x, 0.f) : x;
        }
        *(float4*)(Crow + tx * 4)      = make_float4(v[0], v[1], v[2], v[3]);
        *(float4*)(Crow + 64 + tx * 4) = make_float4(v[4], v[5], v[6], v[7]);
    }
}

// Gconv: e = bmm(Anorm, AX) + UX (dot from zero, then elementwise add).
__global__ __launch_bounds__(256, 2)
void gconv_kernel(const float* __restrict__ adj, const float* __restrict__ Y,
                  float* __restrict__ e)
{
    const int b = blockIdx.x, tid = threadIdx.x;
    __shared__ float sA[NN * NN];
    __shared__ float cs[NN];
    __shared__ float An[NN][NN + 2];

    if (tid < NN * NN) sA[tid] = adj[(size_t)b * NN * NN + tid];
    __syncthreads();
    if (tid < NN) {
        float s = 0.f;
#pragma unroll
        for (int i = 0; i < NN; i++) s = __fadd_rn(s, sA[i * NN + tid]);
        cs[tid] = fmaxf(s, 1e-12f);
    }
    __syncthreads();
    if (tid < NN * NN) {
        int i = tid / NN, j = tid - i * NN;
        An[i][j] = __fdiv_rn(sA[tid], cs[j]);
    }
    __syncthreads();

    const float* Yb = Y + (size_t)b * NN * WN;
    float* eb = e + (size_t)b * NN * OUTF;
    for (int f = tid; f < OUTF; f += blockDim.x) {
        float ax[NN], ux[NN];
#pragma unroll
        for (int j = 0; j < NN; j++) {
            ax[j] = Yb[j * WN + f];
            ux[j] = Yb[j * WN + OUTF + f];
        }
#pragma unroll
        for (int i = 0; i < NN; i++) {
            float d = __fmul_rn(An[i][0], ax[0]);
#pragma unroll
            for (int j = 1; j < NN; j++) d = fmaf(An[i][j], ax[j], d);
            eb[i * OUTF + f] = __fadd_rn(d, ux[i]);
        }
    }
}

// Affinity gram (sequential fp32) + softmax(200*s) + 20 Sinkhorn iters with
// FTZ emulation at every tiny-value production site.
__global__ void affinity_kernel(const float* __restrict__ Mx, const float* __restrict__ E2,
                                float* __restrict__ s_out)
{
    const int b = blockIdx.x, tid = threadIdx.x;
    __shared__ float sM[NN][129];
    __shared__ float sE[NN][129];
    __shared__ float S[NN][NN + 1];

    const float* Mb = Mx + (size_t)b * NN * OUTF;
    const float* Eb = E2 + (size_t)b * NN * OUTF;
    const int i = tid / NN, j = tid - i * NN;
    float acc = 0.f;

    for (int d0 = 0; d0 < OUTF; d0 += 128) {
        for (int t = tid; t < NN * 128; t += 256) {
            int r = t >> 7, c = t & 127;
            sM[r][c] = Mb[r * OUTF + d0 + c];
            sE[r][c] = Eb[r * OUTF + d0 + c];
        }
        __syncthreads();
        if (tid < NN * NN) {
#pragma unroll 8
            for (int c = 0; c < 128; c++)
                acc = fmaf(sM[i][c], sE[j][c], acc);
        }
        __syncthreads();
    }
    if (tid < NN * NN) S[i][j] = acc;
    __syncthreads();

    if (tid < NN) {
        float t[NN], m = -__int_as_float(0x7f800000);
#pragma unroll
        for (int jj = 0; jj < NN; jj++) {
            t[jj] = __fmul_rn(200.f, S[tid][jj]);
            m = fmaxf(m, t[jj]);
        }
        float p[NN], sum = 0.f;
#pragma unroll
        for (int jj = 0; jj < NN; jj++) {
            p[jj] = ftzf(expf(__fadd_rn(t[jj], -m)));
            sum = __fadd_rn(sum, p[jj]);
        }
#pragma unroll
        for (int jj = 0; jj < NN; jj++)
            S[tid][jj] = ftzf(__fdiv_rn(p[jj], sum));
    }
    __syncthreads();

    for (int it = 0; it < 20; it++) {
        if ((it & 1) == 0) {
            if (tid < NN) {
                float sum = 0.f;
#pragma unroll
                for (int jj = 0; jj < NN; jj++) sum = __fadd_rn(sum, S[tid][jj]);
                sum = __fadd_rn(sum, 1e-10f);
#pragma unroll
                for (int jj = 0; jj < NN; jj++)
                    S[tid][jj] = ftzf(__fdiv_rn(S[tid][jj], sum));
            }
        } else {
            if (tid < NN) {
                float sum = 0.f;
#pragma unroll
                for (int ii = 0; ii < NN; ii++) sum = __fadd_rn(sum, S[ii][tid]);
                sum = __fadd_rn(sum, 1e-10f);
#pragma unroll
                for (int ii = 0; ii < NN; ii++)
                    S[ii][tid] = ftzf(__fdiv_rn(S[ii][tid], sum));
            }
        }
        __syncthreads();
    }
    if (tid < NN * NN) s_out[(size_t)b * NN * NN + tid] = S[i][j];
}

// Fusion: dot from zero over the contraction index, then add feat.
__global__ void fuse_kernel(const float* __restrict__ f1, const float* __restrict__ f2,
                            const float* __restrict__ s,
                            float* __restrict__ o1, float* __restrict__ o2)
{
    const int b = blockIdx.y;
    const int f = blockIdx.x * blockDim.x + threadIdx.x;
    __shared__ float S[NN * NN];
    if (threadIdx.x < NN * NN) S[threadIdx.x] = s[(size_t)b * NN * NN + threadIdx.x];
    __syncthreads();

    const float* f1b = f1 + (size_t)b * NN * INF;
    const float* f2b = f2 + (size_t)b * NN * INF;
    float* o1b = o1 + (size_t)b * NN * INF;
    float* o2b = o2 + (size_t)b * NN * INF;

    float x1[NN], x2[NN];
#pragma unroll
    for (int r = 0; r < NN; r++) { x1[r] = f1b[r * INF + f]; x2[r] = f2b[r * INF + f]; }
#pragma unroll
    for (int i = 0; i < NN; i++) {
        float d = __fmul_rn(S[i * NN], x2[0]);
#pragma unroll
        for (int jj = 1; jj < NN; jj++) d = fmaf(S[i * NN + jj], x2[jj], d);
        o1b[i * INF + f] = __fadd_rn(x1[i], d);
    }
#pragma unroll
    for (int jj = 0; jj < NN; jj++) {
        float d = __fmul_rn(S[jj], x1[0]);
#pragma unroll
        for (int ii = 1; ii < NN; ii++) d = fmaf(S[ii * NN + jj], x1[ii], d);
        o2b[jj * INF + f] = __fadd_rn(x2[jj], d);
    }
}

static float* symaddr(const void* sym) {
    void* p = nullptr;
    cudaGetSymbolAddress(&p, sym);
    return (float*)p;
}

extern "C" void kernel_launch(void* const* d_in, const int* in_sizes, int n_in,
                              void* d_out, int out_size)
{
    const float* feat1  = (const float*)d_in[0];
    const float* feat2  = (const float*)d_in[1];
    const float* adj    = (const float*)d_in[2];
    const float* a_fc_w = (const float*)d_in[3];
    const float* a_fc_b = (const float*)d_in[4];
    const float* u_fc_w = (const float*)d_in[5];
    const float* u_fc_b = (const float*)d_in[6];
    const float* aff_A  = (const float*)d_in[7];

    float* out   = (float*)d_out;
    float* s_out = out;
    float* out1  = out + (size_t)BATCH * NN * NN;
    float* out2  = out1 + (size_t)BATCH * NN * INF;

    float* Wp = symaddr(g_Wpack);
    float* bp = symaddr(g_bpack);
    float* Y1 = symaddr(g_Y1);
    float* Y2 = symaddr(g_Y2);
    float* e1 = symaddr(g_e1);
    float* e2 = symaddr(g_e2);
    float* M1 = symaddr(g_M1);

    pack_w_kernel<<<(INF * OUTF + 255) / 256, 256>>>(a_fc_w, a_fc_b, u_fc_w, u_fc_b);

    dim3 g1(WN / 128, MROWS / 128);
    sgemm_kernel<<<g1, 256>>>(feat1, Wp, Y1, INF, WN, bp, 1);
    sgemm_kernel<<<g1, 256>>>(feat2, Wp, Y2, INF, WN, bp, 1);

    gconv_kernel<<<BATCH, 256>>>(adj, Y1, e1);
    gconv_kernel<<<BATCH, 256>>>(adj, Y2, e2);

    dim3 g2(OUTF / 128, MROWS / 128);
    sgemm_kernel<<<g2, 256>>>(e1, aff_A, M1, OUTF, OUTF, nullptr, 0);

    affinity_kernel<<<BATCH, 256>>>(M1, e2, s_out);

    dim3 g3(INF / 256, BATCH);
    fuse_kernel<<<g3, 256>>>(feat1, feat2, s_out, out1, out2);
}